// round 16
// baseline (speedup 1.0000x reference)
#include <cuda_runtime.h>
#include <cuda_fp16.h>
#include <cstdint>

#define S_ 512
#define B_ 64
#define D_ 1024
#define H_ 1024
#define G4_ 4096
#define HB_ (B_ * H_)
#define PRE_T (B_ * G4_)
#define NCTA 128
#define TPB 512

__device__ __half g_Wih0h [G4_ * D_];
__device__ __half g_Wih0l [G4_ * D_];
__device__ __half g_Whh0h [G4_ * H_];
__device__ __half g_Whh0l [G4_ * H_];
__device__ __half g_Wcat1h[G4_ * 2 * H_];
__device__ __half g_Wcat1l[G4_ * 2 * H_];
__device__ float  g_pre0f [(size_t)S_ * PRE_T];
__device__ float  g_hr0f[2][HB_];
__device__ float  g_hr1f[2][HB_];
__device__ float2 g_p0[2][B_][NCTA];
__device__ float2 g_p1[2][B_][NCTA];
__device__ float  g_beff0[G4_], g_beff1[G4_];
__device__ unsigned g_barcnt;

// SMEM layout (bytes)
#define SW1_OFF 0        // 32*2056*2 = 131584
#define SW0_OFF 131584   // 32*1032*2 = 66048
#define AH0_OFF 197632   // 64*128B = 8192  (zbuf 8448B aliases AH0+AL0)
#define AL0_OFF 205824
#define AH1_OFF 214016
#define AL1_OFF 222208
#define SMEM_BYTES 230400

__device__ __forceinline__ void mma16816(float* c,
    uint32_t a0, uint32_t a1, uint32_t a2, uint32_t a3, uint32_t b0, uint32_t b1)
{
    asm volatile(
        "mma.sync.aligned.m16n8k16.row.col.f32.f16.f16.f32 "
        "{%0,%1,%2,%3}, {%4,%5,%6,%7}, {%8,%9}, {%0,%1,%2,%3};\n"
        : "+f"(c[0]), "+f"(c[1]), "+f"(c[2]), "+f"(c[3])
        : "r"(a0), "r"(a1), "r"(a2), "r"(a3), "r"(b0), "r"(b1));
}
__device__ __forceinline__ void ldsm4(uint32_t& r0, uint32_t& r1, uint32_t& r2, uint32_t& r3, uint32_t a)
{
    asm volatile("ldmatrix.sync.aligned.m8n8.x4.shared.b16 {%0,%1,%2,%3}, [%4];"
        : "=r"(r0), "=r"(r1), "=r"(r2), "=r"(r3) : "r"(a));
}
__device__ __forceinline__ float sigf_(float x) { return 1.0f / (1.0f + __expf(-x)); }

__device__ __forceinline__ void gbar(unsigned& target) {
    __syncthreads();
    if (threadIdx.x == 0) {
        __threadfence();
        atomicAdd(&g_barcnt, 1u);
        target += NCTA;
        volatile unsigned* p = &g_barcnt;
        unsigned spins = 0;
        while (*p < target) {
            __nanosleep(32);
            if (++spins > 100000000u) break;
        }
        __threadfence();
    }
    __syncthreads();
}

// stats for row tid>>3, result in every thread's registers
__device__ __forceinline__ void finalize_reg(const float2* p, int tid, float& m, float& rs) {
    int b = tid >> 3, q = tid & 7;
    const float2* src = p + b * NCTA + q * 16;
    float s = 0.f, ss = 0.f;
    #pragma unroll
    for (int i = 0; i < 16; i++) { float2 u = __ldcg(src + i); s += u.x; ss += u.y; }
    s += __shfl_xor_sync(~0u, s, 1); ss += __shfl_xor_sync(~0u, ss, 1);
    s += __shfl_xor_sync(~0u, s, 2); ss += __shfl_xor_sync(~0u, ss, 2);
    s += __shfl_xor_sync(~0u, s, 4); ss += __shfl_xor_sync(~0u, ss, 4);
    m = s * (1.0f / H_);
    float var = ss * (1.0f / H_) - m * m;
    rs = rsqrtf(var + 1e-5f);
}

// split 8 fp32 into hi/lo fp16 and store as one int4 each
__device__ __forceinline__ void stage2(char* hiP, char* loP, const float* v) {
    uint32_t h[4], l[4];
    #pragma unroll
    for (int i = 0; i < 4; i++) {
        __half hx = __float2half_rn(v[2*i]), hy = __float2half_rn(v[2*i+1]);
        __half lx = __float2half_rn(v[2*i] - __half2float(hx));
        __half ly = __float2half_rn(v[2*i+1] - __half2float(hy));
        __half2 hh = __halves2half2(hx, hy), ll = __halves2half2(lx, ly);
        h[i] = *(uint32_t*)&hh; l[i] = *(uint32_t*)&ll;
    }
    *(int4*)hiP = make_int4(h[0], h[1], h[2], h[3]);
    *(int4*)loP = make_int4(l[0], l[1], l[2], l[3]);
}

__global__ __launch_bounds__(1024) void init_all(
    const float* __restrict__ Wih0, const float* __restrict__ Whh0,
    const float* __restrict__ Wih1, const float* __restrict__ Whh1,
    const float* __restrict__ g0)
{
    int i = blockIdx.x * blockDim.x + threadIdx.x;
    {
        int n = i >> 11, k = i & 2047;
        float w = (k < 1024) ? Wih1[n * 1024 + k] * g0[k] : Whh1[n * 1024 + (k - 1024)];
        __half hi = __float2half_rn(w);
        g_Wcat1h[i] = hi;
        g_Wcat1l[i] = __float2half_rn(w - __half2float(hi));
    }
    if (i < G4_ * D_) {
        float w = Wih0[i];
        __half hi = __float2half_rn(w);
        g_Wih0h[i] = hi;
        g_Wih0l[i] = __float2half_rn(w - __half2float(hi));
        w = Whh0[i] * g0[i & 1023];
        hi = __float2half_rn(w);
        g_Whh0h[i] = hi;
        g_Whh0l[i] = __float2half_rn(w - __half2float(hi));
    }
    if (i == 0) g_barcnt = 0u;
}

// beff0 = bih0+bhh0 + Whh0.(g0*be0 folded: Whh0 row dot be0) ; beff1 = bih1+bhh1 + Wih1.be0
__global__ __launch_bounds__(256) void fold_bias(
    const float* __restrict__ Whh0, const float* __restrict__ Wih1,
    const float* __restrict__ bih0, const float* __restrict__ bhh0,
    const float* __restrict__ bih1, const float* __restrict__ bhh1,
    const float* __restrict__ be0)
{
    int w = blockIdx.x * 8 + (threadIdx.x >> 5);
    int lane = threadIdx.x & 31;
    const float* row = (w < 4096) ? (Whh0 + (size_t)w * 1024) : (Wih1 + (size_t)(w - 4096) * 1024);
    float s = 0.f;
    for (int k = lane; k < 1024; k += 32) s += row[k] * be0[k];
    #pragma unroll
    for (int o = 16; o; o >>= 1) s += __shfl_xor_sync(~0u, s, o);
    if (!lane) {
        if (w < 4096) g_beff0[w] = bih0[w] + bhh0[w] + s;
        else { int r = w - 4096; g_beff1[r] = bih1[r] + bhh1[r] + s; }
    }
}

__global__ __launch_bounds__(256) void pre_gemm(const float* __restrict__ X)
{
    int n0 = blockIdx.x << 6;
    size_t m0 = (size_t)blockIdx.y << 7;
    int w = threadIdx.x >> 5, lane = threadIdx.x & 31;
    int g = lane >> 2, t = lane & 3;
    size_t mr = m0 + (w << 4) + g;

    const float* X0 = X + mr * D_ + (t << 1);
    const float* X1 = X0 + 8 * D_;

    float acc[8][4];
    #pragma unroll
    for (int s = 0; s < 8; s++) { acc[s][0]=acc[s][1]=acc[s][2]=acc[s][3]=0.f; }

    for (int k = 0; k < D_; k += 16) {
        uint32_t ah[4], al[4];
        float2 f;
        #pragma unroll
        for (int q = 0; q < 4; q++) {
            const float* src = (q & 1) ? X1 : X0;
            int ko = k + ((q >> 1) << 3);
            f = *(const float2*)(src + ko);
            __half hx = __float2half_rn(f.x), hy = __float2half_rn(f.y);
            __half lx = __float2half_rn(f.x - __half2float(hx));
            __half ly = __float2half_rn(f.y - __half2float(hy));
            __half2 hh = __halves2half2(hx, hy), ll = __halves2half2(lx, ly);
            ah[q] = *(uint32_t*)&hh; al[q] = *(uint32_t*)&ll;
        }
        #pragma unroll
        for (int s = 0; s < 8; s++) {
            size_t roff = (size_t)(n0 + s * 8 + g) * D_ + (t << 1) + k;
            uint32_t bh0 = *(const uint32_t*)(g_Wih0h + roff);
            uint32_t bh1 = *(const uint32_t*)(g_Wih0h + roff + 8);
            uint32_t bl0 = *(const uint32_t*)(g_Wih0l + roff);
            uint32_t bl1 = *(const uint32_t*)(g_Wih0l + roff + 8);
            mma16816(acc[s], ah[0], ah[1], ah[2], ah[3], bh0, bh1);
            mma16816(acc[s], al[0], al[1], al[2], al[3], bh0, bh1);
            mma16816(acc[s], ah[0], ah[1], ah[2], ah[3], bl0, bl1);
        }
    }
    #pragma unroll
    for (int s = 0; s < 8; s++) {
        int col = n0 + s * 8 + (t << 1);
        *(float2*)&g_pre0f[mr * G4_ + col]       = make_float2(acc[s][0], acc[s][1]);
        *(float2*)&g_pre0f[(mr + 8) * G4_ + col] = make_float2(acc[s][2], acc[s][3]);
    }
}

__global__ __launch_bounds__(TPB, 1) void lstm_persist(
    const float* __restrict__ bih0, const float* __restrict__ bhh0,
    const float* __restrict__ g0f,  const float* __restrict__ be0f,
    const float* __restrict__ g1f,  const float* __restrict__ be1f,
    float* __restrict__ out, int has_tail)
{
    extern __shared__ __align__(16) char smem[];
    __half* sw1  = (__half*)(smem + SW1_OFF);
    __half* sw0  = (__half*)(smem + SW0_OFF);
    float*  zbuf = (float*)(smem + AH0_OFF);
    char*   bufH[2] = { smem + AH0_OFF, smem + AH1_OFF };
    char*   bufL[2] = { smem + AL0_OFF, smem + AL1_OFF };

    const int tid = threadIdx.x;
    const int cta = blockIdx.x;
    const int j0 = cta << 3;
    const int lane = tid & 31, wid = tid >> 5;
    const int ft = lane & 3;
    const int wn = wid & 3, wm = wid >> 2;                 // 4 n-frags x 4 m-tiles
    const int gb = tid >> 3, gjj = tid & 7, gj = j0 + gjj; // gates: 1 col/thread
    const int sb = tid >> 3, su = tid & 7;                 // staging row/unit
    const int stOff = sb * 128 + ((su ^ (sb & 7)) << 4);   // bytes
    // ldmatrix A geometry
    const int arow = (wm << 4) + (lane & 15);
    const int arbase = arow << 7, ar7 = arow & 7;
    const int aeh = (lane >> 4) & 1;
    // B geometry
    const int brow = wn * 8 + (lane >> 2);
    const int nglob = wn * 1024 + j0 + (lane >> 2);

    uint32_t smemU = (uint32_t)__cvta_generic_to_shared(smem);
    uint32_t aHiU[2] = { smemU + AH0_OFF, smemU + AH1_OFF };
    uint32_t aLoU[2] = { smemU + AL0_OFF, smemU + AL1_OFF };

    // preload resident hi weights
    for (int idx = tid; idx < 32 * 128; idx += TPB) {
        int n = idx >> 7, kc = (idx & 127) << 3;
        int row = ((n >> 3) << 10) + j0 + (n & 7);
        *(int4*)&sw0[n * 1032 + kc] = *(const int4*)&g_Whh0h[(size_t)row * 1024 + kc];
    }
    for (int idx = tid; idx < 32 * 256; idx += TPB) {
        int n = idx >> 8, kc = (idx & 255) << 3;
        int row = ((n >> 3) << 10) + j0 + (n & 7);
        *(int4*)&sw1[n * 2056 + kc] = *(const int4*)&g_Wcat1h[(size_t)row * 2048 + kc];
    }
    __syncthreads();

    // per-thread constants
    const float gam0 = __ldg(&g0f[gj]), bet0 = __ldg(&be0f[gj]);
    const float gam1 = __ldg(&g1f[gj]), bet1 = __ldg(&be1f[gj]);
    float b0pl[4], b0ef[4], b1ef[4];
    #pragma unroll
    for (int g = 0; g < 4; g++) {
        int cc = g * 1024 + gj;
        b0pl[g] = __ldg(&bih0[cc]) + __ldg(&bhh0[cc]);
        b0ef[g] = g_beff0[cc];
        b1ef[g] = g_beff1[cc];
    }

    float c0r = 0.f, c1r = 0.f, h0p = 0.f, h1p = 0.f;
    float m0 = 0.f, rs0 = 0.f, m1, rs1;
    unsigned target = 0;

    for (int t = 0; t < S_; t++) {
        const int par = t & 1, parp = par ^ 1;
        const bool live = (t > 0);

        // prefetch pre0 gate operands (consumed after gemm0)
        size_t pb = (size_t)t * PRE_T + (size_t)gb * G4_ + gj;
        float pi = __ldcg(&g_pre0f[pb]);
        float pf = __ldcg(&g_pre0f[pb + 1024]);
        float pg = __ldcg(&g_pre0f[pb + 2048]);
        float po = __ldcg(&g_pre0f[pb + 3072]);

        // ---------- PHASE A: finish step t-1 output ----------
        if (live) {
            finalize_reg(&g_p1[parp][0][0], tid, m1, rs1);
            float h0n = (h0p - m0) * rs0 * gam0 + bet0;
            float o = (h1p - m1) * rs1 * gam1 + bet1 + h0n;
            out[(size_t)(t - 1) * HB_ + gb * H_ + gj] = o;
        }

        // ---------- gemm0: K=1024, 16 chunks, double-buffered ----------
        {
            float v[8];
            uint32_t wl[2][8];
            const float* hsrc = &g_hr0f[parp][sb * H_ + su * 8];
            const __half* wp0 = g_Whh0l + (size_t)nglob * 1024 + (ft << 1);
            if (live) {
                float4 a = __ldcg((const float4*)hsrc);
                float4 b = __ldcg((const float4*)(hsrc + 4));
                v[0]=a.x; v[1]=a.y; v[2]=a.z; v[3]=a.w; v[4]=b.x; v[5]=b.y; v[6]=b.z; v[7]=b.w;
            }
            #pragma unroll
            for (int kk = 0; kk < 4; kk++) {
                wl[0][2*kk]   = __ldg((const uint32_t*)(wp0 + kk * 16));
                wl[0][2*kk+1] = __ldg((const uint32_t*)(wp0 + kk * 16 + 8));
            }
            {
                float vn[8];
                #pragma unroll
                for (int i = 0; i < 8; i++) vn[i] = live ? (v[i] - m0) * rs0 : 0.f;
                stage2(bufH[0] + stOff, bufL[0] + stOff, vn);
            }
            __syncthreads();

            float acc[4] = {0,0,0,0};
            for (int c = 0; c < 16; c++) {
                int cb = c & 1, nb = cb ^ 1;
                if (c < 15) {
                    if (live) {
                        const float* s = hsrc + (c + 1) * 64;
                        float4 a = __ldcg((const float4*)s);
                        float4 b = __ldcg((const float4*)(s + 4));
                        v[0]=a.x; v[1]=a.y; v[2]=a.z; v[3]=a.w; v[4]=b.x; v[5]=b.y; v[6]=b.z; v[7]=b.w;
                    }
                    const __half* wp = wp0 + (c + 1) * 64;
                    #pragma unroll
                    for (int kk = 0; kk < 4; kk++) {
                        wl[nb][2*kk]   = __ldg((const uint32_t*)(wp + kk * 16));
                        wl[nb][2*kk+1] = __ldg((const uint32_t*)(wp + kk * 16 + 8));
                    }
                }
                const __half* bhR = sw0 + brow * 1032 + c * 64 + (ft << 1);
                #pragma unroll
                for (int kk = 0; kk < 4; kk++) {
                    uint32_t bh0 = *(const uint32_t*)(bhR + (kk << 4));
                    uint32_t bh1 = *(const uint32_t*)(bhR + (kk << 4) + 8);
                    uint32_t uoff = arbase + (uint32_t)(((((kk << 1) + aeh)) ^ ar7) << 4);
                    uint32_t a0, a1, a2, a3, l0, l1, l2, l3;
                    ldsm4(a0, a1, a2, a3, aHiU[cb] + uoff);
                    ldsm4(l0, l1, l2, l3, aLoU[cb] + uoff);
                    mma16816(acc, a0, a1, a2, a3, bh0, bh1);
                    mma16816(acc, l0, l1, l2, l3, bh0, bh1);
                    mma16816(acc, a0, a1, a2, a3, wl[cb][2*kk], wl[cb][2*kk+1]);
                }
                if (c < 15) {
                    float vn[8];
                    #pragma unroll
                    for (int i = 0; i < 8; i++) vn[i] = live ? (v[i] - m0) * rs0 : 0.f;
                    stage2(bufH[nb] + stOff, bufL[nb] + stOff, vn);
                }
                __syncthreads();
            }
            int r = (wm << 4) + (lane >> 2), colz = (wn << 3) + (ft << 1);
            zbuf[r * 33 + colz]           = acc[0];
            zbuf[r * 33 + colz + 1]       = acc[1];
            zbuf[(r + 8) * 33 + colz]     = acc[2];
            zbuf[(r + 8) * 33 + colz + 1] = acc[3];
            __syncthreads();
        }

        // ---------- gates0 ----------
        {
            const float* zr = zbuf + gb * 33;
            float zi = zr[gjj]      + pi + (live ? b0ef[0] : b0pl[0]);
            float zf = zr[8 + gjj]  + pf + (live ? b0ef[1] : b0pl[1]);
            float zg = zr[16 + gjj] + pg + (live ? b0ef[2] : b0pl[2]);
            float zo = zr[24 + gjj] + po + (live ? b0ef[3] : b0pl[3]);
            c0r = sigf_(zf) * c0r + sigf_(zi) * tanhf(zg);
            float h = sigf_(zo) * tanhf(c0r);
            h0p = h;
            g_hr0f[par][gb * H_ + gj] = h;
            float ps = h, ss = h * h;
            ps += __shfl_xor_sync(~0u, ps, 1); ss += __shfl_xor_sync(~0u, ss, 1);
            ps += __shfl_xor_sync(~0u, ps, 2); ss += __shfl_xor_sync(~0u, ss, 2);
            ps += __shfl_xor_sync(~0u, ps, 4); ss += __shfl_xor_sync(~0u, ss, 4);
            if ((lane & 7) == 0) g_p0[par][gb][cta] = make_float2(ps, ss);
        }

        gbar(target);
        finalize_reg(&g_p0[par][0][0], tid, m0, rs0);

        // ---------- gemm1: K=2048, 32 chunks, double-buffered ----------
        {
            float v[8];
            uint32_t wl[2][8];
            const float* hsrc = &g_hr0f[par][sb * H_ + su * 8];
            const float* osrc = out + (size_t)(t - 1) * HB_ + sb * H_ + su * 8;
            const __half* wp0 = g_Wcat1l + (size_t)nglob * 2048 + (ft << 1);
            {
                float4 a = __ldcg((const float4*)hsrc);
                float4 b = __ldcg((const float4*)(hsrc + 4));
                v[0]=a.x; v[1]=a.y; v[2]=a.z; v[3]=a.w; v[4]=b.x; v[5]=b.y; v[6]=b.z; v[7]=b.w;
            }
            #pragma unroll
            for (int kk = 0; kk < 4; kk++) {
                wl[0][2*kk]   = __ldg((const uint32_t*)(wp0 + kk * 16));
                wl[0][2*kk+1] = __ldg((const uint32_t*)(wp0 + kk * 16 + 8));
            }
            {
                float vn[8];
                #pragma unroll
                for (int i = 0; i < 8; i++) vn[i] = (v[i] - m0) * rs0;
                stage2(bufH[0] + stOff, bufL[0] + stOff, vn);
            }
            __syncthreads();

            float acc[4] = {0,0,0,0};
            for (int c = 0; c < 32; c++) {
                int cb = c & 1, nb = cb ^ 1;
                if (c < 31) {
                    int cn = c + 1;
                    if (cn < 16) {
                        const float* s = hsrc + cn * 64;
                        float4 a = __ldcg((const float4*)s);
                        float4 b = __ldcg((const float4*)(s + 4));
                        v[0]=a.x; v[1]=a.y; v[2]=a.z; v[3]=a.w; v[4]=b.x; v[5]=b.y; v[6]=b.z; v[7]=b.w;
                    } else if (live) {
                        const float* s = osrc + (cn - 16) * 64;
                        float4 a = __ldcg((const float4*)s);
                        float4 b = __ldcg((const float4*)(s + 4));
                        v[0]=a.x; v[1]=a.y; v[2]=a.z; v[3]=a.w; v[4]=b.x; v[5]=b.y; v[6]=b.z; v[7]=b.w;
                    }
                    const __half* wp = wp0 + cn * 64;
                    #pragma unroll
                    for (int kk = 0; kk < 4; kk++) {
                        wl[nb][2*kk]   = __ldg((const uint32_t*)(wp + kk * 16));
                        wl[nb][2*kk+1] = __ldg((const uint32_t*)(wp + kk * 16 + 8));
                    }
                }
                const __half* bhR = sw1 + brow * 2056 + c * 64 + (ft << 1);
                #pragma unroll
                for (int kk = 0; kk < 4; kk++) {
                    uint32_t bh0 = *(const uint32_t*)(bhR + (kk << 4));
                    uint32_t bh1 = *(const uint32_t*)(bhR + (kk << 4) + 8);
                    uint32_t uoff = arbase + (uint32_t)(((((kk << 1) + aeh)) ^ ar7) << 4);
                    uint32_t a0, a1, a2, a3, l0, l1, l2, l3;
                    ldsm4(a0, a1, a2, a3, aHiU[cb] + uoff);
                    ldsm4(l0, l1, l2, l3, aLoU[cb] + uoff);
                    mma16816(acc, a0, a1, a2, a3, bh0, bh1);
                    mma16816(acc, l0, l1, l2, l3, bh0, bh1);
                    mma16816(acc, a0, a1, a2, a3, wl[cb][2*kk], wl[cb][2*kk+1]);
                }
                if (c < 31) {
                    int cn = c + 1;
                    float vn[8];
                    if (cn < 16) {
                        #pragma unroll
                        for (int i = 0; i < 8; i++) vn[i] = (v[i] - m0) * rs0;
                    } else if (live) {
                        #pragma unroll
                        for (int i = 0; i < 8; i++) vn[i] = v[i];
                    } else {
                        #pragma unroll
                        for (int i = 0; i < 8; i++) vn[i] = 0.f;
                    }
                    stage2(bufH[nb] + stOff, bufL[nb] + stOff, vn);
                }
                __syncthreads();
            }
            int r = (wm << 4) + (lane >> 2), colz = (wn << 3) + (ft << 1);
            zbuf[r * 33 + colz]           = acc[0];
            zbuf[r * 33 + colz + 1]       = acc[1];
            zbuf[(r + 8) * 33 + colz]     = acc[2];
            zbuf[(r + 8) * 33 + colz + 1] = acc[3];
            __syncthreads();
        }

        // ---------- gates1 ----------
        {
            const float* zr = zbuf + gb * 33;
            float zi = zr[gjj]      + b1ef[0];
            float zf = zr[8 + gjj]  + b1ef[1];
            float zg = zr[16 + gjj] + b1ef[2];
            float zo = zr[24 + gjj] + b1ef[3];
            c1r = sigf_(zf) * c1r + sigf_(zi) * tanhf(zg);
            float h = sigf_(zo) * tanhf(c1r);
            h1p = h;
            g_hr1f[par][gb * H_ + gj] = h;
            float ps = h, ss = h * h;
            ps += __shfl_xor_sync(~0u, ps, 1); ss += __shfl_xor_sync(~0u, ss, 1);
            ps += __shfl_xor_sync(~0u, ps, 2); ss += __shfl_xor_sync(~0u, ss, 2);
            ps += __shfl_xor_sync(~0u, ps, 4); ss += __shfl_xor_sync(~0u, ss, 4);
            if ((lane & 7) == 0) g_p1[par][gb][cta] = make_float2(ps, ss);
        }

        gbar(target);
    }

    // ---------- EPILOGUE ----------
    {
        finalize_reg(&g_p1[1][0][0], tid, m1, rs1);
        float h0n = (h0p - m0) * rs0 * gam0 + bet0;
        float o = (h1p - m1) * rs1 * gam1 + bet1 + h0n;
        out[(size_t)(S_ - 1) * HB_ + gb * H_ + gj] = o;
        if (has_tail) {
            float* tail = out + (size_t)S_ * HB_;
            tail[gb * H_ + gj]           = h0n;
            tail[HB_ + gb * H_ + gj]     = c0r;
            tail[2 * HB_ + gb * H_ + gj] = o;
            tail[3 * HB_ + gb * H_ + gj] = c1r;
        }
    }
}

extern "C" void kernel_launch(void* const* d_in, const int* in_sizes, int n_in,
                              void* d_out, int out_size) {
    const float* X    = (const float*)d_in[0];
    const float* Wih0 = (const float*)d_in[1];
    const float* Whh0 = (const float*)d_in[2];
    const float* bih0 = (const float*)d_in[3];
    const float* bhh0 = (const float*)d_in[4];
    const float* g0   = (const float*)d_in[5];
    const float* be0  = (const float*)d_in[6];
    const float* Wih1 = (const float*)d_in[7];
    const float* Whh1 = (const float*)d_in[8];
    const float* bih1 = (const float*)d_in[9];
    const float* bhh1 = (const float*)d_in[10];
    const float* g1   = (const float*)d_in[11];
    const float* be1  = (const float*)d_in[12];
    float* out = (float*)d_out;

    static int smem_set = 0;
    if (!smem_set) {
        cudaFuncSetAttribute(lstm_persist, cudaFuncAttributeMaxDynamicSharedMemorySize, SMEM_BYTES);
        smem_set = 1;
    }

    int has_tail = (out_size >= S_ * HB_ + 4 * HB_) ? 1 : 0;

    init_all<<<8192, 1024>>>(Wih0, Whh0, Wih1, Whh1, g0);
    fold_bias<<<1024, 256>>>(Whh0, Wih1, bih0, bhh0, bih1, bhh1, be0);
    dim3 pg(64, (S_ * B_) / 128);
    pre_gemm<<<pg, 256>>>(X);
    lstm_persist<<<NCTA, TPB, SMEM_BYTES>>>(bih0, bhh0, g0, be0, g1, be1, out, has_tail);
}

// round 17
// speedup vs baseline: 1.5668x; 1.5668x over previous
#include <cuda_runtime.h>
#include <cuda_fp16.h>
#include <cstdint>

#define S_ 512
#define B_ 64
#define D_ 1024
#define H_ 1024
#define G4_ 4096
#define HB_ (B_ * H_)
#define PRE_T (B_ * G4_)
#define NCTA 128
#define TPB 512

__device__ __half g_Wih0h [G4_ * D_];
__device__ __half g_Wih0l [G4_ * D_];
__device__ __half g_Whh0h [G4_ * H_];
__device__ __half g_Whh0l [G4_ * H_];
__device__ __half g_Wcat1h[G4_ * 2 * H_];
__device__ __half g_Wcat1l[G4_ * 2 * H_];
__device__ float  g_pre0f [(size_t)S_ * PRE_T];
__device__ float  g_hr0f[2][HB_];
__device__ float  g_hr1f[2][HB_];
__device__ float2 g_p0[2][B_][NCTA];
__device__ float2 g_p1[2][B_][NCTA];
__device__ float  g_beff0[G4_], g_beff1[G4_];
__device__ unsigned g_barcnt;

// SMEM layout (bytes)
#define SW1_OFF 0        // 32*2056*2 = 131584
#define SW0_OFF 131584   // 32*1032*2 = 66048
#define AHI_OFF 197632   // 64*128B = 8192   (zbuf 8448B aliases AHI+ALO head)
#define ALO_OFF 205824   // 8192
#define WLO_OFF 214016   // 32*72*2 = 4608
#define SMEM_BYTES 218624

__device__ __forceinline__ void mma16816(float* c,
    uint32_t a0, uint32_t a1, uint32_t a2, uint32_t a3, uint32_t b0, uint32_t b1)
{
    asm volatile(
        "mma.sync.aligned.m16n8k16.row.col.f32.f16.f16.f32 "
        "{%0,%1,%2,%3}, {%4,%5,%6,%7}, {%8,%9}, {%0,%1,%2,%3};\n"
        : "+f"(c[0]), "+f"(c[1]), "+f"(c[2]), "+f"(c[3])
        : "r"(a0), "r"(a1), "r"(a2), "r"(a3), "r"(b0), "r"(b1));
}
__device__ __forceinline__ void ldsm4(uint32_t& r0, uint32_t& r1, uint32_t& r2, uint32_t& r3, uint32_t a)
{
    asm volatile("ldmatrix.sync.aligned.m8n8.x4.shared.b16 {%0,%1,%2,%3}, [%4];"
        : "=r"(r0), "=r"(r1), "=r"(r2), "=r"(r3) : "r"(a));
}
__device__ __forceinline__ float sigf_(float x) { return 1.0f / (1.0f + __expf(-x)); }

__device__ __forceinline__ void gbar(unsigned& target) {
    __syncthreads();
    if (threadIdx.x == 0) {
        __threadfence();
        atomicAdd(&g_barcnt, 1u);
        target += NCTA;
        volatile unsigned* p = &g_barcnt;
        unsigned spins = 0;
        while (*p < target) {
            __nanosleep(32);
            if (++spins > 100000000u) break;
        }
        __threadfence();
    }
    __syncthreads();
}

// stats for row tid>>3; result broadcast into registers of all 8 lanes of that row
__device__ __forceinline__ void finalize_reg(const float2* p, int tid, float& m, float& rs) {
    int b = tid >> 3, q = tid & 7;
    const float2* src = p + b * NCTA + q * 16;
    float s = 0.f, ss = 0.f;
    #pragma unroll
    for (int i = 0; i < 16; i++) { float2 u = __ldcg(src + i); s += u.x; ss += u.y; }
    s += __shfl_xor_sync(~0u, s, 1); ss += __shfl_xor_sync(~0u, ss, 1);
    s += __shfl_xor_sync(~0u, s, 2); ss += __shfl_xor_sync(~0u, ss, 2);
    s += __shfl_xor_sync(~0u, s, 4); ss += __shfl_xor_sync(~0u, ss, 4);
    m = s * (1.0f / H_);
    float var = ss * (1.0f / H_) - m * m;
    rs = rsqrtf(var + 1e-5f);
}

// split 8 fp32 into hi/lo fp16; one int4 store each
__device__ __forceinline__ void stage2(char* hiP, char* loP, const float* v) {
    uint32_t h[4], l[4];
    #pragma unroll
    for (int i = 0; i < 4; i++) {
        __half hx = __float2half_rn(v[2*i]), hy = __float2half_rn(v[2*i+1]);
        __half lx = __float2half_rn(v[2*i] - __half2float(hx));
        __half ly = __float2half_rn(v[2*i+1] - __half2float(hy));
        __half2 hh = __halves2half2(hx, hy), ll = __halves2half2(lx, ly);
        h[i] = *(uint32_t*)&hh; l[i] = *(uint32_t*)&ll;
    }
    *(int4*)hiP = make_int4(h[0], h[1], h[2], h[3]);
    *(int4*)loP = make_int4(l[0], l[1], l[2], l[3]);
}

__global__ __launch_bounds__(1024) void init_all(
    const float* __restrict__ Wih0, const float* __restrict__ Whh0,
    const float* __restrict__ Wih1, const float* __restrict__ Whh1,
    const float* __restrict__ g0)
{
    int i = blockIdx.x * blockDim.x + threadIdx.x;
    {
        int n = i >> 11, k = i & 2047;
        float w = (k < 1024) ? Wih1[n * 1024 + k] * g0[k] : Whh1[n * 1024 + (k - 1024)];
        __half hi = __float2half_rn(w);
        g_Wcat1h[i] = hi;
        g_Wcat1l[i] = __float2half_rn(w - __half2float(hi));
    }
    if (i < G4_ * D_) {
        float w = Wih0[i];
        __half hi = __float2half_rn(w);
        g_Wih0h[i] = hi;
        g_Wih0l[i] = __float2half_rn(w - __half2float(hi));
        w = Whh0[i] * g0[i & 1023];
        hi = __float2half_rn(w);
        g_Whh0h[i] = hi;
        g_Whh0l[i] = __float2half_rn(w - __half2float(hi));
    }
    if (i == 0) g_barcnt = 0u;
}

__global__ __launch_bounds__(256) void fold_bias(
    const float* __restrict__ Whh0, const float* __restrict__ Wih1,
    const float* __restrict__ bih0, const float* __restrict__ bhh0,
    const float* __restrict__ bih1, const float* __restrict__ bhh1,
    const float* __restrict__ be0)
{
    int w = blockIdx.x * 8 + (threadIdx.x >> 5);
    int lane = threadIdx.x & 31;
    const float* row = (w < 4096) ? (Whh0 + (size_t)w * 1024) : (Wih1 + (size_t)(w - 4096) * 1024);
    float s = 0.f;
    for (int k = lane; k < 1024; k += 32) s += row[k] * be0[k];
    #pragma unroll
    for (int o = 16; o; o >>= 1) s += __shfl_xor_sync(~0u, s, o);
    if (!lane) {
        if (w < 4096) g_beff0[w] = bih0[w] + bhh0[w] + s;
        else { int r = w - 4096; g_beff1[r] = bih1[r] + bhh1[r] + s; }
    }
}

__global__ __launch_bounds__(256) void pre_gemm(const float* __restrict__ X)
{
    int n0 = blockIdx.x << 6;
    size_t m0 = (size_t)blockIdx.y << 7;
    int w = threadIdx.x >> 5, lane = threadIdx.x & 31;
    int g = lane >> 2, t = lane & 3;
    size_t mr = m0 + (w << 4) + g;

    const float* X0 = X + mr * D_ + (t << 1);
    const float* X1 = X0 + 8 * D_;

    float acc[8][4];
    #pragma unroll
    for (int s = 0; s < 8; s++) { acc[s][0]=acc[s][1]=acc[s][2]=acc[s][3]=0.f; }

    for (int k = 0; k < D_; k += 16) {
        uint32_t ah[4], al[4];
        float2 f;
        #pragma unroll
        for (int q = 0; q < 4; q++) {
            const float* src = (q & 1) ? X1 : X0;
            int ko = k + ((q >> 1) << 3);
            f = *(const float2*)(src + ko);
            __half hx = __float2half_rn(f.x), hy = __float2half_rn(f.y);
            __half lx = __float2half_rn(f.x - __half2float(hx));
            __half ly = __float2half_rn(f.y - __half2float(hy));
            __half2 hh = __halves2half2(hx, hy), ll = __halves2half2(lx, ly);
            ah[q] = *(uint32_t*)&hh; al[q] = *(uint32_t*)&ll;
        }
        #pragma unroll
        for (int s = 0; s < 8; s++) {
            size_t roff = (size_t)(n0 + s * 8 + g) * D_ + (t << 1) + k;
            uint32_t bh0 = *(const uint32_t*)(g_Wih0h + roff);
            uint32_t bh1 = *(const uint32_t*)(g_Wih0h + roff + 8);
            uint32_t bl0 = *(const uint32_t*)(g_Wih0l + roff);
            uint32_t bl1 = *(const uint32_t*)(g_Wih0l + roff + 8);
            mma16816(acc[s], ah[0], ah[1], ah[2], ah[3], bh0, bh1);
            mma16816(acc[s], al[0], al[1], al[2], al[3], bh0, bh1);
            mma16816(acc[s], ah[0], ah[1], ah[2], ah[3], bl0, bl1);
        }
    }
    #pragma unroll
    for (int s = 0; s < 8; s++) {
        int col = n0 + s * 8 + (t << 1);
        *(float2*)&g_pre0f[mr * G4_ + col]       = make_float2(acc[s][0], acc[s][1]);
        *(float2*)&g_pre0f[(mr + 8) * G4_ + col] = make_float2(acc[s][2], acc[s][3]);
    }
}

__global__ __launch_bounds__(TPB, 1) void lstm_persist(
    const float* __restrict__ bih0, const float* __restrict__ bhh0,
    const float* __restrict__ g0f,  const float* __restrict__ be0f,
    const float* __restrict__ g1f,  const float* __restrict__ be1f,
    float* __restrict__ out, int has_tail)
{
    extern __shared__ __align__(16) char smem[];
    __half* sw1  = (__half*)(smem + SW1_OFF);
    __half* sw0  = (__half*)(smem + SW0_OFF);
    __half* sWlo = (__half*)(smem + WLO_OFF);
    float*  zbuf = (float*)(smem + AHI_OFF);
    char*   bufH = smem + AHI_OFF;
    char*   bufL = smem + ALO_OFF;

    const int tid = threadIdx.x;
    const int cta = blockIdx.x;
    const int j0 = cta << 3;
    const int lane = tid & 31, wid = tid >> 5;
    const int ft = lane & 3;
    const int wn = wid & 3, wm = wid >> 2;                 // 4 n-frags x 4 m-tiles
    const int gb = tid >> 3, gjj = tid & 7, gj = j0 + gjj; // gates: 1 col/thread
    const int sb = tid >> 3, su = tid & 7;                 // staging row/unit
    const int stOff = sb * 128 + ((su ^ (sb & 7)) << 4);   // bytes
    // ldmatrix A geometry
    const int arow = (wm << 4) + (lane & 15);
    const int arbase = arow << 7, ar7 = arow & 7;
    const int aeh = (lane >> 4) & 1;
    // B geometry
    const int brow = wn * 8 + (lane >> 2);
    // Wlo staging (tid<256): row wr, segment wseg
    const int wr = tid >> 3, wseg = tid & 7;
    const int wRglob = ((wr >> 3) << 10) + j0 + (wr & 7);

    uint32_t smemU = (uint32_t)__cvta_generic_to_shared(smem);
    uint32_t aHiU = smemU + AHI_OFF, aLoU = smemU + ALO_OFF;

    for (int idx = tid; idx < 32 * 128; idx += TPB) {
        int n = idx >> 7, kc = (idx & 127) << 3;
        int row = ((n >> 3) << 10) + j0 + (n & 7);
        *(int4*)&sw0[n * 1032 + kc] = *(const int4*)&g_Whh0h[(size_t)row * 1024 + kc];
    }
    for (int idx = tid; idx < 32 * 256; idx += TPB) {
        int n = idx >> 8, kc = (idx & 255) << 3;
        int row = ((n >> 3) << 10) + j0 + (n & 7);
        *(int4*)&sw1[n * 2056 + kc] = *(const int4*)&g_Wcat1h[(size_t)row * 2048 + kc];
    }
    __syncthreads();

    const float gam0 = __ldg(&g0f[gj]), bet0 = __ldg(&be0f[gj]);
    const float gam1 = __ldg(&g1f[gj]), bet1 = __ldg(&be1f[gj]);
    float b0pl[4], b0ef[4], b1ef[4];
    #pragma unroll
    for (int g = 0; g < 4; g++) {
        int cc = g * 1024 + gj;
        b0pl[g] = __ldg(&bih0[cc]) + __ldg(&bhh0[cc]);
        b0ef[g] = g_beff0[cc];
        b1ef[g] = g_beff1[cc];
    }

    float c0r = 0.f, c1r = 0.f, h0p = 0.f, h1p = 0.f;
    float m0 = 0.f, rs0 = 0.f, m1, rs1;
    unsigned target = 0;

    for (int t = 0; t < S_; t++) {
        const int par = t & 1, parp = par ^ 1;
        const bool live = (t > 0);

        size_t pb = (size_t)t * PRE_T + (size_t)gb * G4_ + gj;
        float pi = __ldcg(&g_pre0f[pb]);
        float pf = __ldcg(&g_pre0f[pb + 1024]);
        float pg = __ldcg(&g_pre0f[pb + 2048]);
        float po = __ldcg(&g_pre0f[pb + 3072]);

        if (live) {
            finalize_reg(&g_p1[parp][0][0], tid, m1, rs1);
            float h0n = (h0p - m0) * rs0 * gam0 + bet0;
            float o = (h1p - m1) * rs1 * gam1 + bet1 + h0n;
            out[(size_t)(t - 1) * HB_ + gb * H_ + gj] = o;
        }

        // ---------- gemm0: K=1024, 16 chunks, 2-sync cadence ----------
        {
            float v[8]; int4 wpf = make_int4(0,0,0,0);
            const float* hsrc = &g_hr0f[parp][sb * H_ + su * 8];
            if (live) {
                float4 a = __ldcg((const float4*)hsrc);
                float4 b = __ldcg((const float4*)(hsrc + 4));
                v[0]=a.x; v[1]=a.y; v[2]=a.z; v[3]=a.w; v[4]=b.x; v[5]=b.y; v[6]=b.z; v[7]=b.w;
            }
            if (tid < 256) wpf = *(const int4*)&g_Whh0l[(size_t)wRglob * 1024 + (wseg << 3)];

            float acc0[4] = {0,0,0,0}, acc1[4] = {0,0,0,0};
            for (int c = 0; c < 16; c++) {
                __syncthreads();   // prev chunk MMAs done; buffers free
                {
                    float vn[8];
                    #pragma unroll
                    for (int i = 0; i < 8; i++) vn[i] = live ? (v[i] - m0) * rs0 : 0.f;
                    stage2(bufH + stOff, bufL + stOff, vn);
                }
                if (tid < 256) *(int4*)&sWlo[wr * 72 + (wseg << 3)] = wpf;
                __syncthreads();
                if (c + 1 < 16) {
                    if (live) {
                        const float* s = hsrc + (c + 1) * 64;
                        float4 a = __ldcg((const float4*)s);
                        float4 b = __ldcg((const float4*)(s + 4));
                        v[0]=a.x; v[1]=a.y; v[2]=a.z; v[3]=a.w; v[4]=b.x; v[5]=b.y; v[6]=b.z; v[7]=b.w;
                    }
                    if (tid < 256) wpf = *(const int4*)&g_Whh0l[(size_t)wRglob * 1024 + ((c + 1) << 6) + (wseg << 3)];
                }
                const __half* bhR = sw0 + brow * 1032 + c * 64 + (ft << 1);
                const __half* blR = sWlo + brow * 72 + (ft << 1);
                #pragma unroll
                for (int kk = 0; kk < 4; kk++) {
                    uint32_t bh0 = *(const uint32_t*)(bhR + (kk << 4));
                    uint32_t bh1 = *(const uint32_t*)(bhR + (kk << 4) + 8);
                    uint32_t bl0 = *(const uint32_t*)(blR + (kk << 4));
                    uint32_t bl1 = *(const uint32_t*)(blR + (kk << 4) + 8);
                    uint32_t uoff = arbase + (uint32_t)(((((kk << 1) + aeh)) ^ ar7) << 4);
                    uint32_t a0, a1, a2, a3, l0, l1, l2, l3;
                    ldsm4(a0, a1, a2, a3, aHiU + uoff);
                    ldsm4(l0, l1, l2, l3, aLoU + uoff);
                    mma16816(acc0, a0, a1, a2, a3, bh0, bh1);
                    mma16816(acc1, l0, l1, l2, l3, bh0, bh1);
                    if (kk & 1) mma16816(acc1, a0, a1, a2, a3, bl0, bl1);
                    else        mma16816(acc0, a0, a1, a2, a3, bl0, bl1);
                }
            }
            __syncthreads();
            int r = (wm << 4) + (lane >> 2), colz = (wn << 3) + (ft << 1);
            zbuf[r * 33 + colz]           = acc0[0] + acc1[0];
            zbuf[r * 33 + colz + 1]       = acc0[1] + acc1[1];
            zbuf[(r + 8) * 33 + colz]     = acc0[2] + acc1[2];
            zbuf[(r + 8) * 33 + colz + 1] = acc0[3] + acc1[3];
            __syncthreads();
        }

        // ---------- gates0 ----------
        {
            const float* zr = zbuf + gb * 33;
            float zi = zr[gjj]      + pi + (live ? b0ef[0] : b0pl[0]);
            float zf = zr[8 + gjj]  + pf + (live ? b0ef[1] : b0pl[1]);
            float zg = zr[16 + gjj] + pg + (live ? b0ef[2] : b0pl[2]);
            float zo = zr[24 + gjj] + po + (live ? b0ef[3] : b0pl[3]);
            c0r = sigf_(zf) * c0r + sigf_(zi) * tanhf(zg);
            float h = sigf_(zo) * tanhf(c0r);
            h0p = h;
            g_hr0f[par][gb * H_ + gj] = h;
            float ps = h, ss = h * h;
            ps += __shfl_xor_sync(~0u, ps, 1); ss += __shfl_xor_sync(~0u, ss, 1);
            ps += __shfl_xor_sync(~0u, ps, 2); ss += __shfl_xor_sync(~0u, ss, 2);
            ps += __shfl_xor_sync(~0u, ps, 4); ss += __shfl_xor_sync(~0u, ss, 4);
            if ((lane & 7) == 0) g_p0[par][gb][cta] = make_float2(ps, ss);
        }

        gbar(target);
        finalize_reg(&g_p0[par][0][0], tid, m0, rs0);

        // ---------- gemm1: K=2048, 32 chunks ----------
        {
            float v[8]; int4 wpf = make_int4(0,0,0,0);
            const float* hsrc = &g_hr0f[par][sb * H_ + su * 8];
            const float* osrc = out + (size_t)(t - 1) * HB_ + sb * H_ + su * 8;
            {
                float4 a = __ldcg((const float4*)hsrc);
                float4 b = __ldcg((const float4*)(hsrc + 4));
                v[0]=a.x; v[1]=a.y; v[2]=a.z; v[3]=a.w; v[4]=b.x; v[5]=b.y; v[6]=b.z; v[7]=b.w;
            }
            if (tid < 256) wpf = *(const int4*)&g_Wcat1l[(size_t)wRglob * 2048 + (wseg << 3)];

            float acc0[4] = {0,0,0,0}, acc1[4] = {0,0,0,0};
            for (int c = 0; c < 32; c++) {
                __syncthreads();
                {
                    float vn[8];
                    if (c < 16) {
                        #pragma unroll
                        for (int i = 0; i < 8; i++) vn[i] = (v[i] - m0) * rs0;
                    } else if (live) {
                        #pragma unroll
                        for (int i = 0; i < 8; i++) vn[i] = v[i];
                    } else {
                        #pragma unroll
                        for (int i = 0; i < 8; i++) vn[i] = 0.f;
                    }
                    stage2(bufH + stOff, bufL + stOff, vn);
                }
                if (tid < 256) *(int4*)&sWlo[wr * 72 + (wseg << 3)] = wpf;
                __syncthreads();
                if (c + 1 < 32) {
                    int cn = c + 1;
                    if (cn < 16) {
                        const float* s = hsrc + cn * 64;
                        float4 a = __ldcg((const float4*)s);
                        float4 b = __ldcg((const float4*)(s + 4));
                        v[0]=a.x; v[1]=a.y; v[2]=a.z; v[3]=a.w; v[4]=b.x; v[5]=b.y; v[6]=b.z; v[7]=b.w;
                    } else if (live) {
                        const float* s = osrc + (cn - 16) * 64;
                        float4 a = __ldcg((const float4*)s);
                        float4 b = __ldcg((const float4*)(s + 4));
                        v[0]=a.x; v[1]=a.y; v[2]=a.z; v[3]=a.w; v[4]=b.x; v[5]=b.y; v[6]=b.z; v[7]=b.w;
                    }
                    if (tid < 256) wpf = *(const int4*)&g_Wcat1l[(size_t)wRglob * 2048 + (cn << 6) + (wseg << 3)];
                }
                const __half* bhR = sw1 + brow * 2056 + c * 64 + (ft << 1);
                const __half* blR = sWlo + brow * 72 + (ft << 1);
                #pragma unroll
                for (int kk = 0; kk < 4; kk++) {
                    uint32_t bh0 = *(const uint32_t*)(bhR + (kk << 4));
                    uint32_t bh1 = *(const uint32_t*)(bhR + (kk << 4) + 8);
                    uint32_t bl0 = *(const uint32_t*)(blR + (kk << 4));
                    uint32_t bl1 = *(const uint32_t*)(blR + (kk << 4) + 8);
                    uint32_t uoff = arbase + (uint32_t)(((((kk << 1) + aeh)) ^ ar7) << 4);
                    uint32_t a0, a1, a2, a3, l0, l1, l2, l3;
                    ldsm4(a0, a1, a2, a3, aHiU + uoff);
                    ldsm4(l0, l1, l2, l3, aLoU + uoff);
                    mma16816(acc0, a0, a1, a2, a3, bh0, bh1);
                    mma16816(acc1, l0, l1, l2, l3, bh0, bh1);
                    if (kk & 1) mma16816(acc1, a0, a1, a2, a3, bl0, bl1);
                    else        mma16816(acc0, a0, a1, a2, a3, bl0, bl1);
                }
            }
            __syncthreads();
            int r = (wm << 4) + (lane >> 2), colz = (wn << 3) + (ft << 1);
            zbuf[r * 33 + colz]           = acc0[0] + acc1[0];
            zbuf[r * 33 + colz + 1]       = acc0[1] + acc1[1];
            zbuf[(r + 8) * 33 + colz]     = acc0[2] + acc1[2];
            zbuf[(r + 8) * 33 + colz + 1] = acc0[3] + acc1[3];
            __syncthreads();
        }

        // ---------- gates1 ----------
        {
            const float* zr = zbuf + gb * 33;
            float zi = zr[gjj]      + b1ef[0];
            float zf = zr[8 + gjj]  + b1ef[1];
            float zg = zr[16 + gjj] + b1ef[2];
            float zo = zr[24 + gjj] + b1ef[3];
            c1r = sigf_(zf) * c1r + sigf_(zi) * tanhf(zg);
            float h = sigf_(zo) * tanhf(c1r);
            h1p = h;
            g_hr1f[par][gb * H_ + gj] = h;
            float ps = h, ss = h * h;
            ps += __shfl_xor_sync(~0u, ps, 1); ss += __shfl_xor_sync(~0u, ss, 1);
            ps += __shfl_xor_sync(~0u, ps, 2); ss += __shfl_xor_sync(~0u, ss, 2);
            ps += __shfl_xor_sync(~0u, ps, 4); ss += __shfl_xor_sync(~0u, ss, 4);
            if ((lane & 7) == 0) g_p1[par][gb][cta] = make_float2(ps, ss);
        }

        gbar(target);
    }

    // ---------- EPILOGUE ----------
    {
        finalize_reg(&g_p1[1][0][0], tid, m1, rs1);
        float h0n = (h0p - m0) * rs0 * gam0 + bet0;
        float o = (h1p - m1) * rs1 * gam1 + bet1 + h0n;
        out[(size_t)(S_ - 1) * HB_ + gb * H_ + gj] = o;
        if (has_tail) {
            float* tail = out + (size_t)S_ * HB_;
            tail[gb * H_ + gj]           = h0n;
            tail[HB_ + gb * H_ + gj]     = c0r;
            tail[2 * HB_ + gb * H_ + gj] = o;
            tail[3 * HB_ + gb * H_ + gj] = c1r;
        }
    }
}

extern "C" void kernel_launch(void* const* d_in, const int* in_sizes, int n_in,
                              void* d_out, int out_size) {
    const float* X    = (const float*)d_in[0];
    const float* Wih0 = (const float*)d_in[1];
    const float* Whh0 = (const float*)d_in[2];
    const float* bih0 = (const float*)d_in[3];
    const float* bhh0 = (const float*)d_in[4];
    const float* g0   = (const float*)d_in[5];
    const float* be0  = (const float*)d_in[6];
    const float* Wih1 = (const float*)d_in[7];
    const float* Whh1 = (const float*)d_in[8];
    const float* bih1 = (const float*)d_in[9];
    const float* bhh1 = (const float*)d_in[10];
    const float* g1   = (const float*)d_in[11];
    const float* be1  = (const float*)d_in[12];
    float* out = (float*)d_out;

    static int smem_set = 0;
    if (!smem_set) {
        cudaFuncSetAttribute(lstm_persist, cudaFuncAttributeMaxDynamicSharedMemorySize, SMEM_BYTES);
        smem_set = 1;
    }

    int has_tail = (out_size >= S_ * HB_ + 4 * HB_) ? 1 : 0;

    init_all<<<8192, 1024>>>(Wih0, Whh0, Wih1, Whh1, g0);
    fold_bias<<<1024, 256>>>(Whh0, Wih1, bih0, bhh0, bih1, bhh1, be0);
    dim3 pg(64, (S_ * B_) / 128);
    pre_gemm<<<pg, 256>>>(X);
    lstm_persist<<<NCTA, TPB, SMEM_BYTES>>>(bih0, bhh0, g0, be0, g1, be1, out, has_tail);
}